// round 9
// baseline (speedup 1.0000x reference)
#include <cuda_runtime.h>
#include <math.h>

#define NNODES 1024
#define FD 64
#define MAXB 4
#define SMAX 16384
#define CAP 256          // per-(b,node) bucket capacity; Poisson(16) => P(overflow)~0

// ---- scratch (no allocations allowed) ----
__device__ int            g_cntd [MAXB * NNODES];               // flows with dst == node
__device__ int            g_cnts [MAXB * NNODES];               // flows with src == node
__device__ unsigned       g_listd[MAXB * NNODES * CAP];         // (src<<14) | flowLocal
__device__ unsigned short g_lists[MAXB * NNODES * CAP];         // dst endpoint
__device__ float          g_Wh   [MAXB * NNODES * FD];          // Wh = normalize(node) @ W
__device__ float          g_f1   [MAXB * NNODES];
__device__ float          g_f2   [MAXB * NNODES];

// ------------------------------------------------------------------
// K0: zero the bucket counters (tiny: 32 KB)
// ------------------------------------------------------------------
__global__ void k_zero() {
    int i = blockIdx.x * blockDim.x + threadIdx.x;
    if (i < MAXB * NNODES) { g_cntd[i] = 0; g_cnts[i] = 0; }
}

// ------------------------------------------------------------------
// K1: bin flows into per-(b,node) buckets. One thread per flow.
// 2 small atomics + 2 stores per flow (vs 16 red.v4 + 2 atomicOr before).
// ------------------------------------------------------------------
__global__ void k_build(const int* __restrict__ src,
                        const int* __restrict__ dst,
                        int B, int S) {
    int f = blockIdx.x * blockDim.x + threadIdx.x;
    if (f >= B * S) return;
    int b  = f / S;
    int sl = f - b * S;                 // flow index within batch
    int d  = __ldg(&dst[f]);
    int s  = __ldg(&src[f]);

    int nd = b * NNODES + d;
    int p = atomicAdd(&g_cntd[nd], 1);
    if (p < CAP) g_listd[nd * CAP + p] = ((unsigned)s << 14) | (unsigned)sl;

    int ns = b * NNODES + s;
    int q = atomicAdd(&g_cnts[ns], 1);
    if (q < CAP) g_lists[ns * CAP + q] = (unsigned short)d;
}

// ------------------------------------------------------------------
// K2: gather node features + normalize + Wh = h@W + f1,f2.
// One warp per node; 8 warps/block; W cached in smem.
// Flow list broadcast via shfl; feature loads 128B-coalesced per warp.
// ------------------------------------------------------------------
__global__ void k_nodeproc(const float* __restrict__ ff,
                           const float* __restrict__ W,
                           const float* __restrict__ a1,
                           const float* __restrict__ a2,
                           int BN) {
    __shared__ float sW[FD * FD];
    __shared__ float sh[8][FD];
    int tid = threadIdx.x;
    for (int i = tid; i < FD * FD; i += 256) sW[i] = W[i];
    __syncthreads();

    int warp = tid >> 5, lane = tid & 31;
    int n = blockIdx.x * 8 + warp;
    if (n >= BN) return;

    int cnt = min(g_cntd[n], CAP);
    const unsigned* lst = &g_listd[n * CAP];
    long bbase = (long)(n >> 10) * SMAX;     // batch offset in flows

    float x0 = 0.0f, x1 = 0.0f;
    for (int c0 = 0; c0 < cnt; c0 += 64) {
        int rem = min(cnt - c0, 64);
        unsigned e0 = (lane      < rem) ? lst[c0 + lane]      : 0u;
        unsigned e1 = (lane + 32 < rem) ? lst[c0 + lane + 32] : 0u;
        for (int i = 0; i < rem; i++) {
            unsigned e = __shfl_sync(~0u, (i < 32) ? e0 : e1, i & 31);
            int fl = e & 0x3FFF;
            const float* fp = ff + (bbase + fl) * FD;
            x0 += fp[lane];
            x1 += fp[lane + 32];
        }
    }

    float ss = x0 * x0 + x1 * x1;
    #pragma unroll
    for (int o = 16; o; o >>= 1) ss += __shfl_xor_sync(~0u, ss, o);
    float inv = 1.0f / fmaxf(sqrtf(ss), 1e-12f);

    sh[warp][lane]      = x0 * inv;
    sh[warp][lane + 32] = x1 * inv;
    __syncwarp();

    float w0 = 0.0f, w1 = 0.0f;
    #pragma unroll
    for (int d = 0; d < FD; d++) {
        float hd = sh[warp][d];
        w0 = fmaf(hd, sW[d * FD + lane],      w0);
        w1 = fmaf(hd, sW[d * FD + lane + 32], w1);
    }
    g_Wh[n * FD + lane]      = w0;
    g_Wh[n * FD + lane + 32] = w1;

    float p1 = w0 * a1[lane] + w1 * a1[lane + 32];
    float p2 = w0 * a2[lane] + w1 * a2[lane + 32];
    #pragma unroll
    for (int o = 16; o; o >>= 1) {
        p1 += __shfl_xor_sync(~0u, p1, o);
        p2 += __shfl_xor_sync(~0u, p2, o);
    }
    if (lane == 0) { g_f1[n] = p1; g_f2[n] = p2; }
}

// ------------------------------------------------------------------
// K3: masked softmax attention + elu. One block (128 thr) per row.
// Row bitmask built in SMEM from the two bucket lists (smem atomicOr),
// then: fused compaction + p=exp(leaky(e)) + partial sum (no max
// subtraction: logits are O(10), fp32-exp-safe; masked entries are
// exactly 0 in the reference), block sum, float4 AXPY.
// ------------------------------------------------------------------
__global__ void k_attn(float4* __restrict__ out) {
    __shared__ unsigned s_words[32];
    __shared__ short    s_jl[NNODES];
    __shared__ float    s_pv[NNODES];
    __shared__ float    s_red[4];
    __shared__ float4   s_acc[8][16];
    __shared__ int      s_cnt;

    int row = blockIdx.x;
    int b   = row >> 10;
    int tid = threadIdx.x;
    int warp = tid >> 5;

    const float*  f2  = g_f2 + b * NNODES;
    const float4* Wh4 = (const float4*)(g_Wh + b * NNODES * FD);

    if (tid < 32) s_words[tid] = 0u;
    if (tid == 0) s_cnt = 0;
    __syncthreads();

    // --- build row adjacency mask from bucket lists ---
    int cd = min(g_cntd[row], CAP);
    int cs = min(g_cnts[row], CAP);
    for (int i = tid; i < cd; i += 128) {
        int s = g_listd[row * CAP + i] >> 14;
        atomicOr(&s_words[s >> 5], 1u << (s & 31));
    }
    for (int i = tid; i < cs; i += 128) {
        int d = g_lists[row * CAP + i];
        atomicOr(&s_words[d >> 5], 1u << (d & 31));
    }
    __syncthreads();

    float f1i = g_f1[row];

    // --- fused compaction + p = exp(leaky(e)) + local partial sum ---
    float psum = 0.0f;
    {
        unsigned bits = (s_words[tid >> 2] >> ((tid & 3) * 8)) & 0xFFu;
        if (bits) {
            int n = __popc(bits);
            int off = atomicAdd(&s_cnt, n);
            int jbase = (tid >> 2) * 32 + (tid & 3) * 8;
            while (bits) {
                int bp = __ffs(bits) - 1;
                bits &= bits - 1;
                int j = jbase + bp;
                float e = f1i + f2[j];
                e = e >= 0.0f ? e : 0.2f * e;
                float p = __expf(e);
                s_jl[off] = (short)j;
                s_pv[off] = p;
                off++;
                psum += p;
            }
        }
    }
    #pragma unroll
    for (int o = 16; o; o >>= 1) psum += __shfl_xor_sync(~0u, psum, o);
    if ((tid & 31) == 0) s_red[warp] = psum;
    __syncthreads();
    float s = s_red[0] + s_red[1] + s_red[2] + s_red[3];
    int cnt = s_cnt;

    int g = tid >> 4, sub = tid & 15;
    float4 acc = make_float4(0.0f, 0.0f, 0.0f, 0.0f);
    float scale;

    if (cnt == 0) {
        // fully masked row: uniform softmax -> mean of all Wh rows
        for (int j = g; j < NNODES; j += 8) {
            float4 v = Wh4[j * 16 + sub];
            acc.x += v.x; acc.y += v.y; acc.z += v.z; acc.w += v.w;
        }
        scale = 1.0f / NNODES;
    } else {
        for (int i = g; i < cnt; i += 8) {
            int j   = s_jl[i];
            float p = s_pv[i];
            float4 v = Wh4[j * 16 + sub];
            acc.x = fmaf(p, v.x, acc.x);
            acc.y = fmaf(p, v.y, acc.y);
            acc.z = fmaf(p, v.z, acc.z);
            acc.w = fmaf(p, v.w, acc.w);
        }
        scale = 1.0f / s;
    }

    s_acc[g][sub] = acc;
    __syncthreads();
    if (tid < 16) {
        float4 r = s_acc[0][tid];
        #pragma unroll
        for (int gg = 1; gg < 8; gg++) {
            float4 v = s_acc[gg][tid];
            r.x += v.x; r.y += v.y; r.z += v.z; r.w += v.w;
        }
        r.x *= scale; r.y *= scale; r.z *= scale; r.w *= scale;
        r.x = r.x > 0.0f ? r.x : expm1f(r.x);
        r.y = r.y > 0.0f ? r.y : expm1f(r.y);
        r.z = r.z > 0.0f ? r.z : expm1f(r.z);
        r.w = r.w > 0.0f ? r.w : expm1f(r.w);
        out[row * 16 + tid] = r;
    }
}

// ------------------------------------------------------------------
extern "C" void kernel_launch(void* const* d_in, const int* in_sizes, int n_in,
                              void* d_out, int out_size) {
    const float* ff  = (const float*)d_in[0];
    const int*   src = (const int*)  d_in[1];
    const int*   dst = (const int*)  d_in[2];
    const float* W   = (const float*)d_in[9];
    const float* a1  = (const float*)d_in[10];
    const float* a2  = (const float*)d_in[11];

    int B = out_size / (NNODES * FD);       // 4
    int S = in_sizes[1] / B;                // 16384
    int BN = B * NNODES;

    k_zero<<<(MAXB * NNODES + 255) / 256, 256>>>();

    int flows = B * S;
    k_build<<<(flows + 255) / 256, 256>>>(src, dst, B, S);

    k_nodeproc<<<(BN + 7) / 8, 256>>>(ff, W, a1, a2, BN);

    k_attn<<<BN, 128>>>((float4*)d_out);
}

// round 10
// speedup vs baseline: 1.1677x; 1.1677x over previous
#include <cuda_runtime.h>
#include <math.h>

#define NNODES 1024
#define FD 64
#define MAXB 4

// ---- scratch (no allocations allowed; statically zero-initialized) ----
// INVARIANT: g_node and g_adj are all-zero at every kernel_launch entry.
// k_nodeproc re-zeroes g_node after reading; k_attn re-zeroes g_adj after
// reading. So the invariant is restored by the end of every launch.
__device__ float    g_node[MAXB * NNODES * FD];          // scatter accumulator
__device__ float    g_Wh  [MAXB * NNODES * FD];          // Wh = normalize(node) @ W
__device__ float    g_f1  [MAXB * NNODES];
__device__ float    g_f2  [MAXB * NNODES];
__device__ unsigned g_adj [MAXB * NNODES * (NNODES/32)]; // adjacency bitmask

// ------------------------------------------------------------------
// K1: scatter-add flow features at dst nodes + adjacency bitmask.
// One thread per (flow, 4-dim chunk): 16 threads per flow.
// ------------------------------------------------------------------
__global__ void k_scatter(const float4* __restrict__ ff,
                          const int* __restrict__ src,
                          const int* __restrict__ dst,
                          int B, int S) {
    int t = blockIdx.x * blockDim.x + threadIdx.x;
    int total = B * S * 16;
    if (t >= total) return;
    int flow = t >> 4;
    int c    = t & 15;
    int b    = flow / S;
    int d    = __ldg(&dst[flow]);

    float4 v = ff[t];
    float* p = &g_node[(b * NNODES + d) * FD + c * 4];
    asm volatile("red.global.add.v4.f32 [%0], {%1,%2,%3,%4};"
                 :: "l"(p), "f"(v.x), "f"(v.y), "f"(v.z), "f"(v.w)
                 : "memory");

    if (c == 0) {
        int sI = __ldg(&src[flow]);
        atomicOr(&g_adj[(b * NNODES + sI) * 32 + (d  >> 5)], 1u << (d  & 31));
        atomicOr(&g_adj[(b * NNODES + d ) * 32 + (sI >> 5)], 1u << (sI & 31));
    }
}

// ------------------------------------------------------------------
// K2: h = node / max(||node||,1e-12);  Wh = h @ W;  f1 = Wh·a1;  f2 = Wh·a2
// One warp per node; 8 warps per block; W cached in smem.
// Re-zeroes g_node after reading (restores launch invariant).
// ------------------------------------------------------------------
__global__ void k_nodeproc(const float* __restrict__ W,
                           const float* __restrict__ a1,
                           const float* __restrict__ a2,
                           int BN) {
    __shared__ float sW[FD * FD];
    __shared__ float sh[8][FD];
    int tid = threadIdx.x;
    for (int i = tid; i < FD * FD; i += 256) sW[i] = W[i];
    __syncthreads();

    int warp = tid >> 5, lane = tid & 31;
    int n = blockIdx.x * 8 + warp;
    if (n >= BN) return;

    float x0 = g_node[n * FD + lane];
    float x1 = g_node[n * FD + lane + 32];
    g_node[n * FD + lane]      = 0.0f;     // restore invariant
    g_node[n * FD + lane + 32] = 0.0f;

    float ss = x0 * x0 + x1 * x1;
    #pragma unroll
    for (int o = 16; o; o >>= 1) ss += __shfl_xor_sync(~0u, ss, o);
    float inv = 1.0f / fmaxf(sqrtf(ss), 1e-12f);

    sh[warp][lane]      = x0 * inv;
    sh[warp][lane + 32] = x1 * inv;
    __syncwarp();

    float w0 = 0.0f, w1 = 0.0f;
    #pragma unroll
    for (int d = 0; d < FD; d++) {
        float hd = sh[warp][d];
        w0 = fmaf(hd, sW[d * FD + lane],      w0);
        w1 = fmaf(hd, sW[d * FD + lane + 32], w1);
    }
    g_Wh[n * FD + lane]      = w0;
    g_Wh[n * FD + lane + 32] = w1;

    float p1 = w0 * a1[lane] + w1 * a1[lane + 32];
    float p2 = w0 * a2[lane] + w1 * a2[lane + 32];
    #pragma unroll
    for (int o = 16; o; o >>= 1) {
        p1 += __shfl_xor_sync(~0u, p1, o);
        p2 += __shfl_xor_sync(~0u, p2, o);
    }
    if (lane == 0) { g_f1[n] = p1; g_f2[n] = p2; }
}

// ------------------------------------------------------------------
// K3 (v2 structure + no-max single-exp + float4 AXPY):
// One block (128 thr) per row.
//  - warp0: load mask row, re-zero it (restore invariant), warp-scan
//    popcounts, serial bit-emit compaction (measured-best structure)
//  - single pass: p = exp(leaky(e)) (no max subtraction: logits O(10),
//    fp32-exp-safe; masked entries contribute exactly 0 in reference)
//  - one block sum; float4 AXPY over compacted list (8 groups x 16)
// ------------------------------------------------------------------
__global__ void k_attn(float4* __restrict__ out) {
    __shared__ short  s_jl[NNODES];
    __shared__ float  s_pv[NNODES];
    __shared__ float  s_red[4];
    __shared__ float4 s_acc[8][16];
    __shared__ int    s_cnt;

    int row = blockIdx.x;
    int b   = row >> 10;
    int tid = threadIdx.x;
    int warp = tid >> 5, lane = tid & 31;

    const float*  f2  = g_f2 + b * NNODES;
    const float4* Wh4 = (const float4*)(g_Wh + b * NNODES * FD);
    float f1i = g_f1[row];

    // --- compaction (warp 0) ---
    if (warp == 0) {
        unsigned word = g_adj[row * 32 + lane];
        g_adj[row * 32 + lane] = 0u;       // restore invariant
        int pc = __popc(word);
        int scan = pc;
        #pragma unroll
        for (int o = 1; o < 32; o <<= 1) {
            int v = __shfl_up_sync(~0u, scan, o);
            if (lane >= o) scan += v;
        }
        int excl = scan - pc;
        if (lane == 31) s_cnt = scan;
        int base = lane * 32;
        while (word) {
            int bp = __ffs(word) - 1;
            word &= word - 1;
            s_jl[excl++] = (short)(base + bp);
        }
    }
    __syncthreads();
    int cnt = s_cnt;

    int g = tid >> 4, sub = tid & 15;
    float4 acc = make_float4(0.0f, 0.0f, 0.0f, 0.0f);
    float scale;

    if (cnt == 0) {
        // fully masked row: uniform softmax -> mean of all Wh rows
        for (int j = g; j < NNODES; j += 8) {
            float4 v = Wh4[j * 16 + sub];
            acc.x += v.x; acc.y += v.y; acc.z += v.z; acc.w += v.w;
        }
        scale = 1.0f / NNODES;
    } else {
        // --- single pass: p = exp(leaky(e)), partial sum ---
        float psum = 0.0f;
        for (int i = tid; i < cnt; i += 128) {
            int j = s_jl[i];
            float e = f1i + f2[j];
            e = e >= 0.0f ? e : 0.2f * e;
            float p = __expf(e);
            s_pv[i] = p;
            psum += p;
        }
        #pragma unroll
        for (int o = 16; o; o >>= 1) psum += __shfl_xor_sync(~0u, psum, o);
        if (lane == 0) s_red[warp] = psum;
        __syncthreads();
        float s = s_red[0] + s_red[1] + s_red[2] + s_red[3];

        // --- float4 AXPY over compacted list ---
        for (int i = g; i < cnt; i += 8) {
            int j   = s_jl[i];
            float p = s_pv[i];
            float4 v = Wh4[j * 16 + sub];
            acc.x = fmaf(p, v.x, acc.x);
            acc.y = fmaf(p, v.y, acc.y);
            acc.z = fmaf(p, v.z, acc.z);
            acc.w = fmaf(p, v.w, acc.w);
        }
        scale = 1.0f / s;
    }

    s_acc[g][sub] = acc;
    __syncthreads();
    if (tid < 16) {
        float4 r = s_acc[0][tid];
        #pragma unroll
        for (int gg = 1; gg < 8; gg++) {
            float4 v = s_acc[gg][tid];
            r.x += v.x; r.y += v.y; r.z += v.z; r.w += v.w;
        }
        r.x *= scale; r.y *= scale; r.z *= scale; r.w *= scale;
        r.x = r.x > 0.0f ? r.x : expm1f(r.x);
        r.y = r.y > 0.0f ? r.y : expm1f(r.y);
        r.z = r.z > 0.0f ? r.z : expm1f(r.z);
        r.w = r.w > 0.0f ? r.w : expm1f(r.w);
        out[row * 16 + tid] = r;
    }
}

// ------------------------------------------------------------------
extern "C" void kernel_launch(void* const* d_in, const int* in_sizes, int n_in,
                              void* d_out, int out_size) {
    const float* ff  = (const float*)d_in[0];
    const int*   src = (const int*)  d_in[1];
    const int*   dst = (const int*)  d_in[2];
    const float* W   = (const float*)d_in[9];
    const float* a1  = (const float*)d_in[10];
    const float* a2  = (const float*)d_in[11];

    int B = out_size / (NNODES * FD);       // 4
    int S = in_sizes[1] / B;                // 16384
    int BN = B * NNODES;

    int total = B * S * 16;
    k_scatter<<<(total + 255) / 256, 256>>>((const float4*)ff, src, dst, B, S);

    k_nodeproc<<<(BN + 7) / 8, 256>>>(W, a1, a2, BN);

    k_attn<<<BN, 128>>>((float4*)d_out);
}